// round 9
// baseline (speedup 1.0000x reference)
#include <cuda_runtime.h>
#include <cstdint>
#include <cstddef>

// Problem constants
#define S_LEN 2048
#define I_DIM 4096
#define O_DIM 4096
#define M_DIM 8192            // B*S
#define NGRP  32              // I / 128 groups

// ---------------------------------------------------------------------------
// Scratch (device globals)
// ---------------------------------------------------------------------------
__device__ __align__(16) signed char g_qx[(size_t)M_DIM * I_DIM];  // quantized acts [m][i]
__device__ __align__(16) signed char g_ws[(size_t)O_DIM * I_DIM];  // w_int - zero   [o][i]

// ---------------------------------------------------------------------------
// Fused prep kernel.
// ---------------------------------------------------------------------------
__global__ void prep_kernel(const float* __restrict__ x,
                            const float* __restrict__ act_scale,
                            const int* __restrict__ qweight,
                            const int* __restrict__ weight_zero) {
    if (blockIdx.x < 8192) {
        int idx = blockIdx.x * 256 + threadIdx.x;             // 0 .. O*I/8-1
        int o = idx >> 9;
        int j4 = idx & 511;
        int grp = j4 >> 4;
        int z = weight_zero[o * NGRP + grp];
        int4 v = reinterpret_cast<const int4*>(qweight)[idx];
        signed char w[8];
        w[0] = (signed char)((v.x & 15) - z);  w[1] = (signed char)(((v.x >> 4) & 15) - z);
        w[2] = (signed char)((v.y & 15) - z);  w[3] = (signed char)(((v.y >> 4) & 15) - z);
        w[4] = (signed char)((v.z & 15) - z);  w[5] = (signed char)(((v.z >> 4) & 15) - z);
        w[6] = (signed char)((v.w & 15) - z);  w[7] = (signed char)(((v.w >> 4) & 15) - z);
        reinterpret_cast<uint2*>(g_ws)[idx] = *reinterpret_cast<uint2*>(w);
    } else {
        int idx = (blockIdx.x - 8192) * 256 + threadIdx.x;    // float4 index
        float4 v = reinterpret_cast<const float4*>(x)[idx];
        int m = idx >> 10;
        float s = act_scale[m & (S_LEN - 1)];

        float r0 = rintf(__fdiv_rn(v.x, s));
        float r1 = rintf(__fdiv_rn(v.y, s));
        float r2 = rintf(__fdiv_rn(v.z, s));
        float r3 = rintf(__fdiv_rn(v.w, s));
        r0 = fmaxf(-127.f, fminf(127.f, r0));
        r1 = fmaxf(-127.f, fminf(127.f, r1));
        r2 = fmaxf(-127.f, fminf(127.f, r2));
        r3 = fmaxf(-127.f, fminf(127.f, r3));

        char4 q;
        q.x = (signed char)(int)r0;
        q.y = (signed char)(int)r1;
        q.z = (signed char)(int)r2;
        q.w = (signed char)(int)r3;
        reinterpret_cast<char4*>(g_qx)[idx] = q;
    }
}

// ---------------------------------------------------------------------------
// GEMM helpers
// ---------------------------------------------------------------------------
__device__ __forceinline__ void cp16(unsigned smem_dst, const void* gmem_src) {
    asm volatile("cp.async.cg.shared.global [%0], [%1], 16;\n" :: "r"(smem_dst), "l"(gmem_src));
}

__device__ __forceinline__ void ldsm4(unsigned& r0, unsigned& r1, unsigned& r2,
                                      unsigned& r3, unsigned addr) {
    asm volatile("ldmatrix.sync.aligned.m8n8.x4.shared.b16 {%0,%1,%2,%3}, [%4];"
                 : "=r"(r0), "=r"(r1), "=r"(r2), "=r"(r3) : "r"(addr));
}

__device__ __forceinline__ void mma_s8(int* c, const unsigned* a, const unsigned* b) {
    asm volatile(
        "mma.sync.aligned.m16n8k32.row.col.s32.s8.s8.s32 "
        "{%0,%1,%2,%3},{%4,%5,%6,%7},{%8,%9},{%0,%1,%2,%3};\n"
        : "+r"(c[0]), "+r"(c[1]), "+r"(c[2]), "+r"(c[3])
        : "r"(a[0]), "r"(a[1]), "r"(a[2]), "r"(a[3]), "r"(b[0]), "r"(b[1]));
}

// exact (float)v for |v| < 2^22, without I2F: alu IADD + fma FADD
__device__ __forceinline__ float i2f_exact(int v) {
    return __int_as_float(v + 0x4B400000) - 12582912.0f;
}

// ---------------------------------------------------------------------------
// GEMM: CTA 128x128, K-slab 128 (one group), 256 threads = 8 warps (2M x 4N),
//       warp tile 64x32. 4-stage cp.async ring, prefetch distance 2,
//       ONE __syncthreads per group (drift-safe with 4 stages).
//   Rescale uses magic-number int->float (no I2F) + conflict-free transposed
//   scale loads.
// SMEM: 4 x 32KB stages + 16KB wscale[g][c] = 144KB
// ---------------------------------------------------------------------------
#define NSTAGES    4
#define STAGE_A    16384
#define STAGE_AB   32768
#define SMEM_SCALE (NSTAGES * STAGE_AB)        // 131072
#define SMEM_TOTAL (SMEM_SCALE + 16384)        // 147456

__global__ __launch_bounds__(256, 1)
void gemm_kernel(const float* __restrict__ act_scale,
                 const float* __restrict__ wscale,     // (O, 32)
                 const float* __restrict__ bias,
                 float* __restrict__ out) {
    extern __shared__ char smem[];
    const unsigned smem_base = (unsigned)__cvta_generic_to_shared(smem);

    const int bn = blockIdx.x;              // 0..31
    const int bm = blockIdx.y;              // 0..63
    const int tid = threadIdx.x;
    const int lane = tid & 31;
    const int wid = tid >> 5;
    const int wm = wid >> 2;                // 0..1 (M: 64 rows)
    const int wn = wid & 3;                 // 0..3 (N: 32 cols)

    const signed char* gA = g_qx + (size_t)bm * 128 * I_DIM;
    const signed char* gB = g_ws + (size_t)bn * 128 * I_DIM;

    // stage wscale transposed: sScaleT[g*128 + c] = wscale[(bn*128+c)*32 + g]
    float* sScaleT = reinterpret_cast<float*>(smem + SMEM_SCALE);
    for (int i = tid; i < 4096; i += 256) {
        int c = i >> 5, g = i & 31;
        sScaleT[g * 128 + c] = __ldg(wscale + (size_t)(bn * 128 + c) * NGRP + g);
    }

    // --- slab loader: one 128B K-slab (one group) of A and B ---
    auto load_slab = [&](int g, int buf) {
        unsigned dA = smem_base + buf * STAGE_AB;
        unsigned dB = dA + STAGE_A;
        const char* sAg = reinterpret_cast<const char*>(gA) + g * 128;
        const char* sBg = reinterpret_cast<const char*>(gB) + g * 128;
#pragma unroll
        for (int it = 0; it < 4; ++it) {
            int c = tid + it * 256;         // 0..1023
            int row = c >> 3, unit = c & 7;
            unsigned off = row * 128 + ((unit ^ (row & 7)) << 4);
            cp16(dA + off, sAg + (size_t)row * I_DIM + unit * 16);
            cp16(dB + off, sBg + (size_t)row * I_DIM + unit * 16);
        }
    };

    load_slab(0, 0);
    asm volatile("cp.async.commit_group;\n");
    load_slab(1, 1);
    asm volatile("cp.async.commit_group;\n");

    // per-lane ldmatrix address components
    const int selA_row = ((lane >> 3) & 1) * 8 + (lane & 7);
    const int bhA = lane >> 4;
    const int selB_row = ((lane >> 4) & 1) * 8 + (lane & 7);
    const int bhB = (lane >> 3) & 1;

    float acc_f[4][4][4];
#pragma unroll
    for (int i = 0; i < 4; ++i)
#pragma unroll
        for (int j = 0; j < 4; ++j)
#pragma unroll
            for (int k = 0; k < 4; ++k) acc_f[i][j][k] = 0.f;

    __syncthreads();                        // sScaleT visible

    for (int g = 0; g < NGRP; ++g) {
        if (g + 2 < NGRP) {
            load_slab(g + 2, (g + 2) & (NSTAGES - 1));
            asm volatile("cp.async.commit_group;\n");
            asm volatile("cp.async.wait_group 2;\n");
        } else if (g + 1 < NGRP) {
            asm volatile("cp.async.wait_group 1;\n");
        } else {
            asm volatile("cp.async.wait_group 0;\n");
        }
        __syncthreads();                    // slab g visible from all warps
        // (single sync per group: with 4 stages, buffer (g+2)&3 differs from
        //  any stage still being read by a warp that is at most 1 group behind)

        const unsigned aBase = smem_base + (g & (NSTAGES - 1)) * STAGE_AB;
        const unsigned bBase = aBase + STAGE_A;

        int acc_i[4][4][4];
#pragma unroll
        for (int i = 0; i < 4; ++i)
#pragma unroll
            for (int j = 0; j < 4; ++j)
#pragma unroll
                for (int k = 0; k < 4; ++k) acc_i[i][j][k] = 0;

#pragma unroll
        for (int kk = 0; kk < 4; ++kk) {
            unsigned a[4][4];
            unsigned b[4][2];
#pragma unroll
            for (int mt = 0; mt < 4; ++mt) {
                int row = wm * 64 + mt * 16 + selA_row;
                unsigned slot = (unsigned)((kk * 2 + bhA) ^ (row & 7));
                ldsm4(a[mt][0], a[mt][1], a[mt][2], a[mt][3],
                      aBase + row * 128 + (slot << 4));
            }
#pragma unroll
            for (int p = 0; p < 2; ++p) {
                int row = wn * 32 + p * 16 + selB_row;
                unsigned slot = (unsigned)((kk * 2 + bhB) ^ (row & 7));
                ldsm4(b[2 * p][0], b[2 * p][1], b[2 * p + 1][0], b[2 * p + 1][1],
                      bBase + row * 128 + (slot << 4));
            }
#pragma unroll
            for (int mt = 0; mt < 4; ++mt)
#pragma unroll
                for (int nt = 0; nt < 4; ++nt)
                    mma_s8(acc_i[mt][nt], a[mt], b[nt]);
        }

        // fold exact int32 group sums; no I2F (magic-number conversion is exact
        // for |v| <= 2^22; here |v| <= 128*127*15 = 243840)
#pragma unroll
        for (int nt = 0; nt < 4; ++nt) {
            int c0 = wn * 32 + nt * 8 + 2 * (lane & 3);
            float2 s01 = *reinterpret_cast<const float2*>(&sScaleT[g * 128 + c0]);
#pragma unroll
            for (int mt = 0; mt < 4; ++mt) {
                acc_f[mt][nt][0] += s01.x * i2f_exact(acc_i[mt][nt][0]);
                acc_f[mt][nt][1] += s01.y * i2f_exact(acc_i[mt][nt][1]);
                acc_f[mt][nt][2] += s01.x * i2f_exact(acc_i[mt][nt][2]);
                acc_f[mt][nt][3] += s01.y * i2f_exact(acc_i[mt][nt][3]);
            }
        }
        // no end-of-group __syncthreads: bounded drift is safe with 4 stages
    }

    // --- epilogue: out = s_act[m] * acc + bias[o] ---
#pragma unroll
    for (int mt = 0; mt < 4; ++mt) {
        int r0 = bm * 128 + wm * 64 + mt * 16 + (lane >> 2);
        float sa0 = __ldg(act_scale + (r0 & (S_LEN - 1)));
        float sa1 = __ldg(act_scale + ((r0 + 8) & (S_LEN - 1)));
#pragma unroll
        for (int nt = 0; nt < 4; ++nt) {
            int c0 = bn * 128 + wn * 32 + nt * 8 + 2 * (lane & 3);
            float b0 = __ldg(bias + c0);
            float b1 = __ldg(bias + c0 + 1);
            float2 v0, v1;
            v0.x = sa0 * acc_f[mt][nt][0] + b0;
            v0.y = sa0 * acc_f[mt][nt][1] + b1;
            v1.x = sa1 * acc_f[mt][nt][2] + b0;
            v1.y = sa1 * acc_f[mt][nt][3] + b1;
            *reinterpret_cast<float2*>(&out[(size_t)r0 * O_DIM + c0]) = v0;
            *reinterpret_cast<float2*>(&out[(size_t)(r0 + 8) * O_DIM + c0]) = v1;
        }
    }
}

// ---------------------------------------------------------------------------
// Launch. Inputs: x, qweight, act_scale, weight_scale, weight_zero, bias.
// ---------------------------------------------------------------------------
extern "C" void kernel_launch(void* const* d_in, const int* in_sizes, int n_in,
                              void* d_out, int out_size) {
    const float* x        = (const float*)d_in[0];
    const int*   qweight  = (const int*)d_in[1];
    const float* actscale = (const float*)d_in[2];
    const float* wscale   = (const float*)d_in[3];
    const int*   wzero    = (const int*)d_in[4];
    const float* bias     = (const float*)d_in[5];
    float* out = (float*)d_out;

    prep_kernel<<<40960, 256>>>(x, actscale, qweight, wzero);

    cudaFuncSetAttribute(gemm_kernel,
                         cudaFuncAttributeMaxDynamicSharedMemorySize, SMEM_TOTAL);
    dim3 grid(O_DIM / 128, M_DIM / 128);   // (32, 64)
    gemm_kernel<<<grid, 256, SMEM_TOTAL>>>(actscale, wscale, bias, out);
}

// round 13
// speedup vs baseline: 1.0987x; 1.0987x over previous
#include <cuda_runtime.h>
#include <cstdint>
#include <cstddef>

// Problem constants
#define S_LEN 2048
#define I_DIM 4096
#define O_DIM 4096
#define M_DIM 8192            // B*S
#define NGRP  32              // I / 128 groups

// ---------------------------------------------------------------------------
// Scratch (device globals)
// ---------------------------------------------------------------------------
__device__ __align__(16) signed char g_qx[(size_t)M_DIM * I_DIM];  // quantized acts [m][i]
__device__ __align__(16) signed char g_ws[(size_t)O_DIM * I_DIM];  // w_int - zero   [o][i]

// ---------------------------------------------------------------------------
// Fused prep kernel.
// ---------------------------------------------------------------------------
__global__ void prep_kernel(const float* __restrict__ x,
                            const float* __restrict__ act_scale,
                            const int* __restrict__ qweight,
                            const int* __restrict__ weight_zero) {
    if (blockIdx.x < 8192) {
        int idx = blockIdx.x * 256 + threadIdx.x;             // 0 .. O*I/8-1
        int o = idx >> 9;
        int j4 = idx & 511;
        int grp = j4 >> 4;
        int z = weight_zero[o * NGRP + grp];
        int4 v = reinterpret_cast<const int4*>(qweight)[idx];
        signed char w[8];
        w[0] = (signed char)((v.x & 15) - z);  w[1] = (signed char)(((v.x >> 4) & 15) - z);
        w[2] = (signed char)((v.y & 15) - z);  w[3] = (signed char)(((v.y >> 4) & 15) - z);
        w[4] = (signed char)((v.z & 15) - z);  w[5] = (signed char)(((v.z >> 4) & 15) - z);
        w[6] = (signed char)((v.w & 15) - z);  w[7] = (signed char)(((v.w >> 4) & 15) - z);
        reinterpret_cast<uint2*>(g_ws)[idx] = *reinterpret_cast<uint2*>(w);
    } else {
        int idx = (blockIdx.x - 8192) * 256 + threadIdx.x;    // float4 index
        float4 v = reinterpret_cast<const float4*>(x)[idx];
        int m = idx >> 10;
        float s = act_scale[m & (S_LEN - 1)];

        float r0 = rintf(__fdiv_rn(v.x, s));
        float r1 = rintf(__fdiv_rn(v.y, s));
        float r2 = rintf(__fdiv_rn(v.z, s));
        float r3 = rintf(__fdiv_rn(v.w, s));
        r0 = fmaxf(-127.f, fminf(127.f, r0));
        r1 = fmaxf(-127.f, fminf(127.f, r1));
        r2 = fmaxf(-127.f, fminf(127.f, r2));
        r3 = fmaxf(-127.f, fminf(127.f, r3));

        char4 q;
        q.x = (signed char)(int)r0;
        q.y = (signed char)(int)r1;
        q.z = (signed char)(int)r2;
        q.w = (signed char)(int)r3;
        reinterpret_cast<char4*>(g_qx)[idx] = q;
    }
}

// ---------------------------------------------------------------------------
// GEMM helpers
// ---------------------------------------------------------------------------
__device__ __forceinline__ void cp16(unsigned smem_dst, const void* gmem_src) {
    asm volatile("cp.async.cg.shared.global [%0], [%1], 16;\n" :: "r"(smem_dst), "l"(gmem_src));
}

__device__ __forceinline__ void ldsm4(unsigned& r0, unsigned& r1, unsigned& r2,
                                      unsigned& r3, unsigned addr) {
    asm volatile("ldmatrix.sync.aligned.m8n8.x4.shared.b16 {%0,%1,%2,%3}, [%4];"
                 : "=r"(r0), "=r"(r1), "=r"(r2), "=r"(r3) : "r"(addr));
}

__device__ __forceinline__ void mma_s8(int* c, const unsigned* a, const unsigned* b) {
    asm volatile(
        "mma.sync.aligned.m16n8k32.row.col.s32.s8.s8.s32 "
        "{%0,%1,%2,%3},{%4,%5,%6,%7},{%8,%9},{%0,%1,%2,%3};\n"
        : "+r"(c[0]), "+r"(c[1]), "+r"(c[2]), "+r"(c[3])
        : "r"(a[0]), "r"(a[1]), "r"(a[2]), "r"(a[3]), "r"(b[0]), "r"(b[1]));
}

// named barrier over 256 threads (ids 1 and 2; id 0 is __syncthreads)
__device__ __forceinline__ void half_sync(int id) {
    asm volatile("bar.sync %0, 256;" :: "r"(id) : "memory");
}

// ---------------------------------------------------------------------------
// GEMM: ONE CTA of 512 threads = TWO fully independent 256-thread halves,
//   each with its own 4-stage cp.async ring, own A+B SMEM, own scales, and
//   its own named barrier (bar.sync 1+h, 256). Halves drift independently ->
//   one half's rescale/wait overlaps the other half's MMA stream on the same
//   SMSPs (the phase-lock breaker; replaces the 2-CTA/SM attempt).
//   Half tile: 128(M) x 64(N); 8 warps (4M x 2N), warp tile 32x32.
//   CTA tile: 128 x 128 (halves side-by-side in N).
// SMEM: 2 x (4 x 24KB stages + 8KB scales) = 212,992 B (single CTA opt-in)
// ---------------------------------------------------------------------------
#define NSTAGES     4
#define STAGE_A     16384                      // A: 128 rows x 128B
#define STAGE_B     8192                       // B:  64 rows x 128B
#define STAGE_AB    (STAGE_A + STAGE_B)        // 24576
#define HALF_STAGES (NSTAGES * STAGE_AB)       // 98304
#define HALF_SMEM   (HALF_STAGES + 8192)       // 106496
#define SMEM_TOTAL  (2 * HALF_SMEM)            // 212992

__global__ __launch_bounds__(512, 1)
void gemm_kernel(const float* __restrict__ act_scale,
                 const float* __restrict__ wscale,     // (O, 32)
                 const float* __restrict__ bias,
                 float* __restrict__ out) {
    extern __shared__ char smem[];
    const unsigned smem_base = (unsigned)__cvta_generic_to_shared(smem);

    const int bn = blockIdx.x;              // 0..31  (N tiles of 128)
    const int bm = blockIdx.y;              // 0..63  (M tiles of 128)
    const int tid = threadIdx.x;
    const int lane = tid & 31;
    const int wid = tid >> 5;               // 0..15
    const int half = wid >> 3;              // 0 or 1
    const int htid = tid & 255;             // thread id within half
    const int hw = wid & 7;                 // warp id within half
    const int wm = hw >> 1;                 // 0..3 (M: 32 rows each)
    const int wn = hw & 1;                  // 0..1 (N: 32 cols each)
    const int barid = 1 + half;

    const unsigned hbase = smem_base + half * HALF_SMEM;

    const signed char* gA = g_qx + (size_t)bm * 128 * I_DIM;
    const signed char* gB = g_ws + (size_t)(bn * 128 + half * 64) * I_DIM;

    // per-half transposed scales: sScaleT[g*64 + c] for cols bn*128+half*64+c
    float* sScaleT = reinterpret_cast<float*>(smem + half * HALF_SMEM + HALF_STAGES);
    for (int i = htid; i < 2048; i += 256) {
        int c = i >> 5, g = i & 31;
        sScaleT[g * 64 + c] = __ldg(wscale + (size_t)(bn * 128 + half * 64 + c) * NGRP + g);
    }

    // --- per-half slab loader: A 1024 chunks + B 512 chunks ---
    auto load_slab = [&](int g, int buf) {
        unsigned dA = hbase + buf * STAGE_AB;
        unsigned dB = dA + STAGE_A;
        const char* sAg = reinterpret_cast<const char*>(gA) + g * 128;
        const char* sBg = reinterpret_cast<const char*>(gB) + g * 128;
#pragma unroll
        for (int it = 0; it < 4; ++it) {    // A
            int c = htid + it * 256;
            int row = c >> 3, unit = c & 7;
            unsigned off = row * 128 + ((unit ^ (row & 7)) << 4);
            cp16(dA + off, sAg + (size_t)row * I_DIM + unit * 16);
        }
#pragma unroll
        for (int it = 0; it < 2; ++it) {    // B
            int c = htid + it * 256;
            int row = c >> 3, unit = c & 7;
            unsigned off = row * 128 + ((unit ^ (row & 7)) << 4);
            cp16(dB + off, sBg + (size_t)row * I_DIM + unit * 16);
        }
    };

    load_slab(0, 0);
    asm volatile("cp.async.commit_group;\n");
    load_slab(1, 1);
    asm volatile("cp.async.commit_group;\n");

    // per-lane ldmatrix address components
    const int selA_row = ((lane >> 3) & 1) * 8 + (lane & 7);
    const int bhA = lane >> 4;
    const int selB_row = ((lane >> 4) & 1) * 8 + (lane & 7);
    const int bhB = (lane >> 3) & 1;

    float acc_f[2][4][4];
#pragma unroll
    for (int i = 0; i < 2; ++i)
#pragma unroll
        for (int j = 0; j < 4; ++j)
#pragma unroll
            for (int k = 0; k < 4; ++k) acc_f[i][j][k] = 0.f;

    half_sync(barid);                       // own scales + barrier domain ready

    for (int g = 0; g < NGRP; ++g) {
        if (g + 2 < NGRP) {
            load_slab(g + 2, (g + 2) & (NSTAGES - 1));
            asm volatile("cp.async.commit_group;\n");
            asm volatile("cp.async.wait_group 2;\n");
        } else if (g + 1 < NGRP) {
            asm volatile("cp.async.wait_group 1;\n");
        } else {
            asm volatile("cp.async.wait_group 0;\n");
        }
        half_sync(barid);                   // slab g visible within this half
        // 4 stages make drift-by-one safe: load(g+3) at iter g+1 targets
        // buffer (g+3)&3 != g&3 (the 3-stage version aliased them -> R10 bug)

        const unsigned aBase = hbase + (g & (NSTAGES - 1)) * STAGE_AB;
        const unsigned bBase = aBase + STAGE_A;

        int acc_i[2][4][4];
#pragma unroll
        for (int i = 0; i < 2; ++i)
#pragma unroll
            for (int j = 0; j < 4; ++j)
#pragma unroll
                for (int k = 0; k < 4; ++k) acc_i[i][j][k] = 0;

#pragma unroll
        for (int kk = 0; kk < 4; ++kk) {
            unsigned a[2][4];
            unsigned b[4][2];
#pragma unroll
            for (int mt = 0; mt < 2; ++mt) {
                int row = wm * 32 + mt * 16 + selA_row;
                unsigned slot = (unsigned)((kk * 2 + bhA) ^ (row & 7));
                ldsm4(a[mt][0], a[mt][1], a[mt][2], a[mt][3],
                      aBase + row * 128 + (slot << 4));
            }
#pragma unroll
            for (int p = 0; p < 2; ++p) {   // nt pair p -> nt 2p, 2p+1
                int row = wn * 32 + p * 16 + selB_row;
                unsigned slot = (unsigned)((kk * 2 + bhB) ^ (row & 7));
                ldsm4(b[2 * p][0], b[2 * p][1], b[2 * p + 1][0], b[2 * p + 1][1],
                      bBase + row * 128 + (slot << 4));
            }
#pragma unroll
            for (int mt = 0; mt < 2; ++mt)
#pragma unroll
                for (int nt = 0; nt < 4; ++nt)
                    mma_s8(acc_i[mt][nt], a[mt], b[nt]);
        }

        // fold exact int32 group sums with per-(col,group) scale
#pragma unroll
        for (int nt = 0; nt < 4; ++nt) {
            int c0 = wn * 32 + nt * 8 + 2 * (lane & 3);
            float2 s01 = *reinterpret_cast<const float2*>(&sScaleT[g * 64 + c0]);
#pragma unroll
            for (int mt = 0; mt < 2; ++mt) {
                acc_f[mt][nt][0] += s01.x * (float)acc_i[mt][nt][0];
                acc_f[mt][nt][1] += s01.y * (float)acc_i[mt][nt][1];
                acc_f[mt][nt][2] += s01.x * (float)acc_i[mt][nt][2];
                acc_f[mt][nt][3] += s01.y * (float)acc_i[mt][nt][3];
            }
        }
    }

    // --- epilogue: out = s_act[m] * acc + bias[o] ---
#pragma unroll
    for (int mt = 0; mt < 2; ++mt) {
        int r0 = bm * 128 + wm * 32 + mt * 16 + (lane >> 2);
        float sa0 = __ldg(act_scale + (r0 & (S_LEN - 1)));
        float sa1 = __ldg(act_scale + ((r0 + 8) & (S_LEN - 1)));
#pragma unroll
        for (int nt = 0; nt < 4; ++nt) {
            int c0 = bn * 128 + half * 64 + wn * 32 + nt * 8 + 2 * (lane & 3);
            float b0 = __ldg(bias + c0);
            float b1 = __ldg(bias + c0 + 1);
            float2 v0, v1;
            v0.x = sa0 * acc_f[mt][nt][0] + b0;
            v0.y = sa0 * acc_f[mt][nt][1] + b1;
            v1.x = sa1 * acc_f[mt][nt][2] + b0;
            v1.y = sa1 * acc_f[mt][nt][3] + b1;
            *reinterpret_cast<float2*>(&out[(size_t)r0 * O_DIM + c0]) = v0;
            *reinterpret_cast<float2*>(&out[(size_t)(r0 + 8) * O_DIM + c0]) = v1;
        }
    }
}

// ---------------------------------------------------------------------------
// Launch. Inputs: x, qweight, act_scale, weight_scale, weight_zero, bias.
// ---------------------------------------------------------------------------
extern "C" void kernel_launch(void* const* d_in, const int* in_sizes, int n_in,
                              void* d_out, int out_size) {
    const float* x        = (const float*)d_in[0];
    const int*   qweight  = (const int*)d_in[1];
    const float* actscale = (const float*)d_in[2];
    const float* wscale   = (const float*)d_in[3];
    const int*   wzero    = (const int*)d_in[4];
    const float* bias     = (const float*)d_in[5];
    float* out = (float*)d_out;

    prep_kernel<<<40960, 256>>>(x, actscale, qweight, wzero);

    cudaFuncSetAttribute(gemm_kernel,
                         cudaFuncAttributeMaxDynamicSharedMemorySize, SMEM_TOTAL);
    dim3 grid(O_DIM / 128, M_DIM / 128);   // (32, 64)
    gemm_kernel<<<grid, 512, SMEM_TOTAL>>>(actscale, wscale, bias, out);
}